// round 8
// baseline (speedup 1.0000x reference)
#include <cuda_runtime.h>
#include <math.h>
#include <stdint.h>

// Problem constants
#define B 512
#define N 100
#define D 128
#define H 8
#define DK 16
#define FF 512
#define TD 384          // 3*D
#define M_ROWS (B*N)    // 51200
#define NEGV -1e9f
#define CLIPV 10.0

static __device__ float g_h [ (size_t)M_ROWS * D ];     // hidden state
static __device__ float g_3d[ (size_t)M_ROWS * TD ];    // qkv / hp scratch
static __device__ float g_ff[ (size_t)M_ROWS * FF ];    // ff1 output
static __device__ float g_o [ (size_t)M_ROWS * D ];     // attention output
static __device__ float g_s [ (size_t)M_ROWS * D ];     // pre-BN (residual sum)
static __device__ float g_ef[ (size_t)M_ROWS * D ];     // h @ Wstep[0:128]
static __device__ float g_ed[ (size_t)M_ROWS * D ];     // h @ Wstep[128:256]
static __device__ float g_part32[2][400][128];          // per-block BN partials
static __device__ double g_mean[D], g_rstd[D];
static __device__ double g_wphw[D];                     // Wph @ Wstep
static __device__ float g_fc[B*D], g_q0[B*D];           // fixed_ctx, step-0 query

// ---------------------------------------------------------------------------
// h = x @ init_W + init_b
// ---------------------------------------------------------------------------
__global__ void init_embed_kernel(const float* __restrict__ x,
                                  const float* __restrict__ W,
                                  const float* __restrict__ bias) {
    int idx = blockIdx.x * blockDim.x + threadIdx.x;
    if (idx >= M_ROWS * D) return;
    int i = idx >> 7, d = idx & 127;
    double v = (double)x[i*2] * (double)W[d]
             + (double)x[i*2+1] * (double)W[D + d]
             + (double)bias[d];
    g_h[idx] = (float)v;
}

// ---------------------------------------------------------------------------
// fp32 tiled GEMM with register double-buffering.
// BM=BN=128, BK=16, 256 threads, 8x8 per thread.
// bnstats!=0: also emit per-column (sum, sumsq) partials of the output tile
// into g_part32[*][blockIdx.y][*] (requires gridDim.x==1, Nc==128).
// ---------------------------------------------------------------------------
__global__ __launch_bounds__(256, 2)
void gemm32_kernel(const float* __restrict__ A, const float* __restrict__ W,
                   const float* __restrict__ bias, const float* __restrict__ res,
                   float* __restrict__ C, int M, int K, int Nc, int relu, int bnstats) {
    __shared__ float As[16][132];
    __shared__ float Bs[16][132];
    const int tid = threadIdx.x;
    const int tx = tid & 15, ty = tid >> 4;
    const int row0 = blockIdx.y * 128, col0 = blockIdx.x * 128;
    // loader indices
    const int lar = tid >> 2, lac = (tid & 3) * 4;         // A: rows tid/4 (+64), k-cols
    const int lbr = tid >> 5, lbc = (tid & 31) * 4;        // B: k-rows tid/32 (+8), cols
    float4 pa0, pa1, pb0, pb1;
    float acc[8][8];
#pragma unroll
    for (int i = 0; i < 8; i++)
#pragma unroll
        for (int j = 0; j < 8; j++) acc[i][j] = 0.f;

    // prefetch tile 0
    pa0 = *reinterpret_cast<const float4*>(&A[(size_t)(row0+lar)*K + lac]);
    pa1 = *reinterpret_cast<const float4*>(&A[(size_t)(row0+lar+64)*K + lac]);
    pb0 = *reinterpret_cast<const float4*>(&W[(size_t)(lbr)*Nc + col0 + lbc]);
    pb1 = *reinterpret_cast<const float4*>(&W[(size_t)(lbr+8)*Nc + col0 + lbc]);

    for (int kt = 0; kt < K; kt += 16) {
        // commit prefetched tile to smem
        As[lac+0][lar] = pa0.x; As[lac+1][lar] = pa0.y; As[lac+2][lar] = pa0.z; As[lac+3][lar] = pa0.w;
        As[lac+0][lar+64] = pa1.x; As[lac+1][lar+64] = pa1.y; As[lac+2][lar+64] = pa1.z; As[lac+3][lar+64] = pa1.w;
        *reinterpret_cast<float4*>(&Bs[lbr][lbc]) = pb0;
        *reinterpret_cast<float4*>(&Bs[lbr+8][lbc]) = pb1;
        __syncthreads();
        // prefetch next tile (overlaps with compute below)
        if (kt + 16 < K) {
            pa0 = *reinterpret_cast<const float4*>(&A[(size_t)(row0+lar)*K + kt+16 + lac]);
            pa1 = *reinterpret_cast<const float4*>(&A[(size_t)(row0+lar+64)*K + kt+16 + lac]);
            pb0 = *reinterpret_cast<const float4*>(&W[(size_t)(kt+16+lbr)*Nc + col0 + lbc]);
            pb1 = *reinterpret_cast<const float4*>(&W[(size_t)(kt+16+lbr+8)*Nc + col0 + lbc]);
        }
#pragma unroll
        for (int k = 0; k < 16; k++) {
            float a[8], bb[8];
            float4 a0 = *reinterpret_cast<const float4*>(&As[k][ty*4]);
            float4 a1 = *reinterpret_cast<const float4*>(&As[k][64 + ty*4]);
            float4 b0 = *reinterpret_cast<const float4*>(&Bs[k][tx*4]);
            float4 b1 = *reinterpret_cast<const float4*>(&Bs[k][64 + tx*4]);
            a[0]=a0.x;a[1]=a0.y;a[2]=a0.z;a[3]=a0.w;a[4]=a1.x;a[5]=a1.y;a[6]=a1.z;a[7]=a1.w;
            bb[0]=b0.x;bb[1]=b0.y;bb[2]=b0.z;bb[3]=b0.w;bb[4]=b1.x;bb[5]=b1.y;bb[6]=b1.z;bb[7]=b1.w;
#pragma unroll
            for (int i = 0; i < 8; i++)
#pragma unroll
                for (int j = 0; j < 8; j++) acc[i][j] = fmaf(a[i], bb[j], acc[i][j]);
        }
        __syncthreads();
    }
    float cs[8], cq[8];
#pragma unroll
    for (int j = 0; j < 8; j++) { cs[j] = 0.f; cq[j] = 0.f; }
#pragma unroll
    for (int i = 0; i < 8; i++) {
        int r = row0 + ty*4 + (i < 4 ? i : 60 + i);
#pragma unroll
        for (int j = 0; j < 8; j++) {
            int c = col0 + tx*4 + (j < 4 ? j : 60 + j);
            float v = acc[i][j];
            if (bias) v += bias[c];
            if (res)  v += res[(size_t)r*Nc + c];
            if (relu) v = fmaxf(v, 0.f);
            C[(size_t)r*Nc + c] = v;
            cs[j] += v;
            cq[j] = fmaf(v, v, cq[j]);
        }
    }
    if (bnstats) {
        __syncthreads();
#pragma unroll
        for (int j = 0; j < 8; j++) {
            int c = tx*4 + (j < 4 ? j : 60 + j);
            As[ty][c] = cs[j];
            Bs[ty][c] = cq[j];
        }
        __syncthreads();
        if (tid < 128) {
            float ssum = 0.f, ssq = 0.f;
#pragma unroll
            for (int t = 0; t < 16; t++) { ssum += As[t][tid]; ssq += Bs[t][tid]; }
            g_part32[0][blockIdx.y][tid] = ssum;
            g_part32[1][blockIdx.y][tid] = ssq;
        }
    }
}

// ---------------------------------------------------------------------------
// Fused MHA v4: one block per (b,h), 512 threads.
// ---------------------------------------------------------------------------
#define ATTN_SMEM_BYTES ((3*1700 + 10000) * 4)
__global__ __launch_bounds__(512)
void attn_kernel(const float* __restrict__ qkv, float* __restrict__ o) {
    extern __shared__ float asm_[];
    float* qsh = asm_;            // 100*17
    float* ksh = qsh + 1700;      // 100*17
    float* vsh = ksh + 1700;      // 100*17
    float* psh = vsh + 1700;      // 100*100
    int bh = blockIdx.x;
    int b = bh >> 3, hh = bh & 7;
    int tid = threadIdx.x;
    for (int i = tid; i < 1600; i += 512) {
        int m = i >> 4, d = i & 15;
        const float* base = qkv + (size_t)(b*N + m) * TD + hh*16 + d;
        qsh[m*17 + d] = base[0];
        ksh[m*17 + d] = base[D];
        vsh[m*17 + d] = base[2*D];
    }
    __syncthreads();
    int w = tid >> 5, lane = tid & 31;
    // fused scores + softmax, warp per row (16 warps)
    for (int n = w; n < 100; n += 16) {
        float qreg[16];
        const float* qp = qsh + n*17;
#pragma unroll
        for (int d = 0; d < 16; d++) qreg[d] = qp[d];
        float sc[4];
        float mx = -1e30f;
#pragma unroll
        for (int j = 0; j < 4; j++) {
            int m = lane + 32*j;
            if (m < 100) {
                const float* kp = ksh + m*17;
                float a0 = 0.f, a1 = 0.f;
#pragma unroll
                for (int d = 0; d < 16; d += 2) {
                    a0 = fmaf(qreg[d],   kp[d],   a0);
                    a1 = fmaf(qreg[d+1], kp[d+1], a1);
                }
                sc[j] = (a0 + a1) * 0.25f;
                mx = fmaxf(mx, sc[j]);
            } else sc[j] = -1e30f;
        }
#pragma unroll
        for (int off = 16; off; off >>= 1) mx = fmaxf(mx, __shfl_xor_sync(0xffffffffu, mx, off));
        double sum = 0.0, ev[4];
#pragma unroll
        for (int j = 0; j < 4; j++) {
            int m = lane + 32*j;
            if (m < 100) { ev[j] = exp((double)(sc[j] - mx)); sum += ev[j]; }
            else ev[j] = 0.0;
        }
#pragma unroll
        for (int off = 16; off; off >>= 1) sum += __shfl_xor_sync(0xffffffffu, sum, off);
        double inv = 1.0 / sum;
#pragma unroll
        for (int j = 0; j < 4; j++) {
            int m = lane + 32*j;
            if (m < 100) psh[n*100 + m] = (float)(ev[j] * inv);
        }
    }
    __syncthreads();
    // O = P @ V (fp32)
    for (int idx = tid; idx < 1600; idx += 512) {
        int n = idx >> 4, dk = idx & 15;
        const float* pp = psh + n*100;
        const float* vp = vsh + dk;
        float a0 = 0.f, a1 = 0.f;
#pragma unroll 4
        for (int m = 0; m < 100; m += 2) {
            a0 = fmaf(pp[m],   vp[(m)*17],   a0);
            a1 = fmaf(pp[m+1], vp[(m+1)*17], a1);
        }
        o[(size_t)(b*N + n) * D + hh*16 + dk] = a0 + a1;
    }
}

// ---------------------------------------------------------------------------
// BN finalize: reduce 400 per-block partials (double), store mean/rstd.
// ---------------------------------------------------------------------------
__global__ void bn_stats2_kernel() {
    int c = threadIdx.x;
    double a = 0.0, q = 0.0;
    for (int p = 0; p < 400; p++) { a += (double)g_part32[0][p][c]; q += (double)g_part32[1][p][c]; }
    double mean = a * (1.0 / (double)M_ROWS);
    double var  = q * (1.0 / (double)M_ROWS) - mean*mean;
    g_mean[c] = mean;
    g_rstd[c] = 1.0 / sqrt(var + 1e-5);
}
__global__ void bn_apply_kernel(const float* __restrict__ s, const float* __restrict__ gb,
                                float* __restrict__ h) {
    int idx = blockIdx.x * blockDim.x + threadIdx.x;
    if (idx >= M_ROWS * D) return;
    int d = idx & 127;
    double v = (double)gb[d] * ((double)s[idx] - g_mean[d]) * g_rstd[d] + (double)gb[D + d];
    h[idx] = (float)v;
}

// ---------------------------------------------------------------------------
// wphw[d] = Wph @ Wstep (column d)
// ---------------------------------------------------------------------------
__global__ void wphw_kernel(const float* __restrict__ Wph, const float* __restrict__ Wstep) {
    int d = threadIdx.x;
    double a0 = 0.0, a1 = 0.0;
    for (int k = 0; k < 2*D; k += 2) {
        a0 = fma((double)Wph[k],   (double)Wstep[(k)*D + d],   a0);
        a1 = fma((double)Wph[k+1], (double)Wstep[(k+1)*D + d], a1);
    }
    g_wphw[d] = a0 + a1;
}

// ---------------------------------------------------------------------------
// Per-batch: hm = mean_n(h); fc = hm @ Wf; q0 = fc + wphw
// ---------------------------------------------------------------------------
__global__ void meanfix_kernel(const float* __restrict__ Wf) {
    __shared__ float sh[D];
    int b = blockIdx.x, d = threadIdx.x;
    double a = 0.0;
    for (int n = 0; n < N; n++) a += (double)g_h[(size_t)(b*N + n) * D + d];
    sh[d] = (float)(a * (1.0 / (double)N));
    __syncthreads();
    double fc = 0.0;
    for (int k = 0; k < D; k++) fc = fma((double)sh[k], (double)Wf[k*D + d], fc);
    g_fc[b*D + d] = (float)fc;
    g_q0[b*D + d] = (float)(fc + g_wphw[d]);
}

// ---------------------------------------------------------------------------
// Persistent greedy decode v3 (unchanged from R7). 512 threads, 2 blocks/SM.
// ---------------------------------------------------------------------------
#define HPS2 257
#define DEC_SMEM_BYTES (16 + (N*HPS2 + 128 + 128 + 800 + 128 + 128 + 512 + 100)*4 + 202*4)

__global__ __launch_bounds__(512, 2)
void decode_kernel(const float* __restrict__ x,
                   const float* __restrict__ Wout,
                   float* __restrict__ out) {
    extern __shared__ double dsm[];
    double* sh_ll  = dsm;
    float* sh_hp   = (float*)(dsm + 2);     // 100*257 (gK | gV)
    float* sh_q    = sh_hp + N*HPS2;
    float* sh_qb   = sh_q + D;
    float* sh_c    = sh_qb + D;
    float* sh_g    = sh_c + 800;
    float* sh_g2   = sh_g + D;
    float* sh_part = sh_g2 + D;
    float* sh_lg   = sh_part + 512;
    int*   sh_mask = (int*)(sh_lg + 100);
    int*   sh_pi   = sh_mask + 100;
    int*   sh_ctrl = sh_pi + 100;

    const float NF = 0.08838834764831843f;
    int b = blockIdx.x, tid = threadIdx.x;
    int w = tid >> 5, lane = tid & 31;
    int dd = tid & 127, part = tid >> 7;
    const float* lKg = g_3d + (size_t)b * (N*TD) + 2*D;

    for (int i = tid; i < N*256; i += 512) {
        int n = i >> 8, j = i & 255;
        sh_hp[n*HPS2 + j] = g_3d[(size_t)b * (N*TD) + n*TD + j];
    }
    if (tid < N) sh_mask[tid] = 0;
    if (tid == 0) { sh_ll[0] = 0.0; sh_ctrl[0] = 0; sh_ctrl[1] = 0; }
    __syncthreads();

    for (int s = 0; s < N; s++) {
        if (tid < 128) {
            if (s == 0) {
                sh_q[tid] = g_q0[b*D + tid];
            } else {
                float qb;
                if (s == 1) {
                    qb = g_fc[b*D + tid] + g_ef[(size_t)(b*N + sh_ctrl[0]) * D + tid];
                    sh_qb[tid] = qb;
                } else qb = sh_qb[tid];
                sh_q[tid] = qb + g_ed[(size_t)(b*N + sh_ctrl[1]) * D + tid];
            }
        }
        __syncthreads();
        for (int idx = tid; idx < 800; idx += 512) {
            int hh = idx / 100, n = idx - hh*100;
            const float* kp = sh_hp + n*HPS2 + hh*16;
            const float* qp = sh_q + hh*16;
            float a0 = 0.f, a1 = 0.f;
#pragma unroll
            for (int d2 = 0; d2 < 16; d2 += 2) {
                a0 = fmaf(qp[d2],   kp[d2],   a0);
                a1 = fmaf(qp[d2+1], kp[d2+1], a1);
            }
            sh_c[idx] = sh_mask[n] ? NEGV : (a0 + a1) * NF;
        }
        __syncthreads();
        if (w < 8) {
            int head = w;
            float mx = -1e30f;
            for (int n = lane; n < 100; n += 32) mx = fmaxf(mx, sh_c[head*100 + n]);
#pragma unroll
            for (int off = 16; off; off >>= 1) mx = fmaxf(mx, __shfl_xor_sync(0xffffffffu, mx, off));
            double sum = 0.0, ev[4];
#pragma unroll
            for (int j = 0; j < 4; j++) {
                int n = lane + 32*j;
                if (n < 100) { ev[j] = exp((double)(sh_c[head*100 + n] - mx)); sum += ev[j]; }
                else ev[j] = 0.0;
            }
#pragma unroll
            for (int off = 16; off; off >>= 1) sum += __shfl_xor_sync(0xffffffffu, sum, off);
            double inv = 1.0 / sum;
#pragma unroll
            for (int j = 0; j < 4; j++) {
                int n = lane + 32*j;
                if (n < 100) sh_c[head*100 + n] = (float)(ev[j] * inv);
            }
        }
        __syncthreads();
        {
            int hh = dd >> 4;
            const float* pp = sh_c + hh*100 + part*25;
            const float* vp = sh_hp + (size_t)(part*25) * HPS2 + D + dd;
            float a0 = 0.f, a1 = 0.f;
#pragma unroll 4
            for (int n = 0; n < 24; n += 2) {
                a0 = fmaf(pp[n],   vp[(n)*HPS2],   a0);
                a1 = fmaf(pp[n+1], vp[(n+1)*HPS2], a1);
            }
            a0 = fmaf(pp[24], vp[24*HPS2], a0);
            sh_part[tid] = a0 + a1;
        }
        __syncthreads();
        if (tid < 128) sh_g[tid] = sh_part[tid] + sh_part[tid+128] + sh_part[tid+256] + sh_part[tid+384];
        __syncthreads();
        {
            int k0 = part * 32;
            float a0 = 0.f, a1 = 0.f;
#pragma unroll 4
            for (int k = 0; k < 32; k += 2) {
                a0 = fmaf(sh_g[k0+k],   __ldg(&Wout[(k0+k)*D + dd]),   a0);
                a1 = fmaf(sh_g[k0+k+1], __ldg(&Wout[(k0+k+1)*D + dd]), a1);
            }
            sh_part[tid] = a0 + a1;
        }
        __syncthreads();
        if (tid < 128) sh_g2[tid] = sh_part[tid] + sh_part[tid+128] + sh_part[tid+256] + sh_part[tid+384];
        __syncthreads();
        if (dd < 100) {
            int k0 = part * 32;
            const float* lp = lKg + (size_t)dd * TD + k0;
            float a0 = 0.f, a1 = 0.f;
#pragma unroll
            for (int q4 = 0; q4 < 8; q4++) {
                float4 v = __ldg(reinterpret_cast<const float4*>(lp + q4*4));
                float4 g = *reinterpret_cast<const float4*>(&sh_g2[k0 + q4*4]);
                a0 = fmaf(g.x, v.x, a0); a1 = fmaf(g.y, v.y, a1);
                a0 = fmaf(g.z, v.z, a0); a1 = fmaf(g.w, v.w, a1);
            }
            sh_part[tid] = a0 + a1;
        }
        __syncthreads();
        if (tid < 100) {
            double a = (double)(sh_part[tid] + sh_part[tid+128] + sh_part[tid+256] + sh_part[tid+384]);
            sh_lg[tid] = sh_mask[tid] ? NEGV : (float)(tanh(a * (double)NF) * CLIPV);
        }
        __syncthreads();
        if (w == 0) {
            float mx = -1e30f; int mi = N + 1;
            for (int n = lane; n < N; n += 32) {
                float v = sh_lg[n];
                if (v > mx) { mx = v; mi = n; }
            }
#pragma unroll
            for (int off = 16; off; off >>= 1) {
                float om = __shfl_xor_sync(0xffffffffu, mx, off);
                int   oi = __shfl_xor_sync(0xffffffffu, mi, off);
                if (om > mx || (om == mx && oi < mi)) { mx = om; mi = oi; }
            }
            double sum = 0.0;
            for (int n = lane; n < N; n += 32) sum += exp((double)sh_lg[n] - (double)mx);
#pragma unroll
            for (int off = 16; off; off >>= 1) sum += __shfl_xor_sync(0xffffffffu, sum, off);
            if (lane == 0) {
                double lse = (double)mx + log(sum);
                sh_ll[0] += (double)sh_lg[mi] - lse;
                sh_mask[mi] = 1;
                sh_ctrl[1] = mi;
                if (s == 0) sh_ctrl[0] = mi;
                sh_pi[s] = mi;
                out[2*B + b*N + s] = (float)mi;
            }
        }
        __syncthreads();
    }
    if (tid < N) {
        int a = sh_pi[tid], c = sh_pi[(tid + 1) % N];
        double dx = (double)x[(b*N + a)*2]     - (double)x[(b*N + c)*2];
        double dy = (double)x[(b*N + a)*2 + 1] - (double)x[(b*N + c)*2 + 1];
        sh_lg[tid] = (float)sqrt(dx*dx + dy*dy);
    }
    __syncthreads();
    if (tid == 0) {
        double cst = 0.0;
        for (int t = 0; t < N; t++) cst += (double)sh_lg[t];
        out[b] = (float)cst;
        out[B + b] = (float)sh_ll[0];
    }
}

// ---------------------------------------------------------------------------
extern "C" void kernel_launch(void* const* d_in, const int* in_sizes, int n_in,
                              void* d_out, int out_size) {
    const float* x        = (const float*)d_in[0];
    const float* init_W   = (const float*)d_in[1];
    const float* init_b   = (const float*)d_in[2];
    const float* qkv_W    = (const float*)d_in[3];
    const float* out_W    = (const float*)d_in[4];
    const float* bn1      = (const float*)d_in[5];
    const float* bn2      = (const float*)d_in[6];
    const float* ff1_W    = (const float*)d_in[7];
    const float* ff1_b    = (const float*)d_in[8];
    const float* ff2_W    = (const float*)d_in[9];
    const float* ff2_b    = (const float*)d_in[10];
    const float* Wph      = (const float*)d_in[11];
    const float* nodes_W  = (const float*)d_in[12];
    const float* fixed_W  = (const float*)d_in[13];
    const float* step_W   = (const float*)d_in[14];
    const float* pout_W   = (const float*)d_in[15];
    float* out = (float*)d_out;

    cudaFuncSetAttribute(decode_kernel, cudaFuncAttributeMaxDynamicSharedMemorySize,
                         DEC_SMEM_BYTES + 128);
    cudaFuncSetAttribute(attn_kernel, cudaFuncAttributeMaxDynamicSharedMemorySize,
                         ATTN_SMEM_BYTES + 128);

    float *p_h, *p_3d, *p_ff, *p_o, *p_s, *p_ef, *p_ed;
    cudaGetSymbolAddress((void**)&p_h,  g_h);
    cudaGetSymbolAddress((void**)&p_3d, g_3d);
    cudaGetSymbolAddress((void**)&p_ff, g_ff);
    cudaGetSymbolAddress((void**)&p_o,  g_o);
    cudaGetSymbolAddress((void**)&p_s,  g_s);
    cudaGetSymbolAddress((void**)&p_ef, g_ef);
    cudaGetSymbolAddress((void**)&p_ed, g_ed);

    const int EW = 256;
    int egrid = (M_ROWS * D + EW - 1) / EW;

    init_embed_kernel<<<egrid, EW>>>(x, init_W, init_b);
    wphw_kernel<<<1, 128>>>(Wph, step_W);

    for (int l = 0; l < 2; l++) {
        gemm32_kernel<<<dim3(TD/128, M_ROWS/128), 256>>>(
            p_h, qkv_W + (size_t)l*D*TD, nullptr, nullptr, p_3d, M_ROWS, D, TD, 0, 0);
        attn_kernel<<<B*H, 512, ATTN_SMEM_BYTES + 128>>>(p_3d, p_o);
        // s = o @ Wout + h, with fused BN stats
        gemm32_kernel<<<dim3(D/128, M_ROWS/128), 256>>>(
            p_o, out_W + (size_t)l*D*D, nullptr, p_h, p_s, M_ROWS, D, D, 0, 1);
        bn_stats2_kernel<<<1, 128>>>();
        bn_apply_kernel<<<egrid, EW>>>(p_s, bn1 + (size_t)l*2*D, p_h);
        gemm32_kernel<<<dim3(FF/128, M_ROWS/128), 256>>>(
            p_h, ff1_W + (size_t)l*D*FF, ff1_b + (size_t)l*FF, nullptr, p_ff, M_ROWS, D, FF, 1, 0);
        // s = ff1 @ W2 + b2 + h, with fused BN stats
        gemm32_kernel<<<dim3(D/128, M_ROWS/128), 256>>>(
            p_ff, ff2_W + (size_t)l*FF*D, ff2_b + (size_t)l*D, p_h, p_s, M_ROWS, FF, D, 0, 1);
        bn_stats2_kernel<<<1, 128>>>();
        bn_apply_kernel<<<egrid, EW>>>(p_s, bn2 + (size_t)l*2*D, p_h);
    }

    // decoder precompute
    gemm32_kernel<<<dim3(TD/128, M_ROWS/128), 256>>>(
        p_h, nodes_W, nullptr, nullptr, p_3d, M_ROWS, D, TD, 0, 0);
    gemm32_kernel<<<dim3(D/128, M_ROWS/128), 256>>>(
        p_h, step_W, nullptr, nullptr, p_ef, M_ROWS, D, D, 0, 0);
    gemm32_kernel<<<dim3(D/128, M_ROWS/128), 256>>>(
        p_h, step_W + (size_t)D*D, nullptr, nullptr, p_ed, M_ROWS, D, D, 0, 0);
    meanfix_kernel<<<B, D>>>(fixed_W);

    decode_kernel<<<B, 512, DEC_SMEM_BYTES + 128>>>(x, pout_W, out);
}

// round 9
// speedup vs baseline: 1.0274x; 1.0274x over previous
#include <cuda_runtime.h>
#include <math.h>
#include <stdint.h>

// Problem constants
#define B 512
#define N 100
#define D 128
#define H 8
#define DK 16
#define FF 512
#define TD 384          // 3*D
#define M_ROWS (B*N)    // 51200
#define NEGV -1e9f
#define CLIPV 10.0

static __device__ float g_h [ (size_t)M_ROWS * D ];     // hidden state
static __device__ float g_3d[ (size_t)M_ROWS * TD ];    // qkv / hp scratch
static __device__ float g_ff[ (size_t)M_ROWS * FF ];    // ff1 output
static __device__ float g_o [ (size_t)M_ROWS * D ];     // attention output
static __device__ float g_s [ (size_t)M_ROWS * D ];     // pre-BN (residual sum)
static __device__ float g_ef[ (size_t)M_ROWS * D ];     // h @ Wstep[0:128]
static __device__ float g_ed[ (size_t)M_ROWS * D ];     // h @ Wstep[128:256]
static __device__ float g_part32[2][400][128];          // per-block BN partials
static __device__ double g_mean[D], g_rstd[D];
static __device__ double g_wphw[D];                     // Wph @ Wstep
static __device__ float g_fc[B*D], g_q0[B*D];           // fixed_ctx, step-0 query

// ---------------------------------------------------------------------------
// h = x @ init_W + init_b
// ---------------------------------------------------------------------------
__global__ void init_embed_kernel(const float* __restrict__ x,
                                  const float* __restrict__ W,
                                  const float* __restrict__ bias) {
    int idx = blockIdx.x * blockDim.x + threadIdx.x;
    if (idx >= M_ROWS * D) return;
    int i = idx >> 7, d = idx & 127;
    double v = (double)x[i*2] * (double)W[d]
             + (double)x[i*2+1] * (double)W[D + d]
             + (double)bias[d];
    g_h[idx] = (float)v;
}

// ---------------------------------------------------------------------------
// fp32 tiled GEMM, cp.async double-buffered.
// BM=BN=128, BK=16, 256 threads, 8x8 per thread.
// A tile: [128][20] row-major (16B-aligned rows). B tile: [16][132].
// bnstats!=0: per-column (sum,sumsq) partials -> g_part32[*][blockIdx.y][*]
// (requires gridDim.x==1, Nc==128).
// ---------------------------------------------------------------------------
#define ARS 20
__global__ __launch_bounds__(256, 2)
void gemm32_kernel(const float* __restrict__ A, const float* __restrict__ W,
                   const float* __restrict__ bias, const float* __restrict__ res,
                   float* __restrict__ C, int M, int K, int Nc, int relu, int bnstats) {
    __shared__ float As[2][128][ARS];    // 20.5 KB
    __shared__ float Bs[2][16][132];     // 16.9 KB
    const int tid = threadIdx.x;
    const int tx = tid & 15, ty = tid >> 4;
    const int row0 = blockIdx.y * 128, col0 = blockIdx.x * 128;
    float acc[8][8];
#pragma unroll
    for (int i = 0; i < 8; i++)
#pragma unroll
        for (int j = 0; j < 8; j++) acc[i][j] = 0.f;

    // async tile loader: A 512 chunks (128 rows x 4), B 512 chunks (16 rows x 32)
    auto loadtile = [&](int kt, int buf) {
#pragma unroll
        for (int p = 0; p < 2; p++) {
            int c = tid + p*256;
            int ar = c >> 2, asub = (c & 3) * 4;
            unsigned da = (unsigned)__cvta_generic_to_shared(&As[buf][ar][asub]);
            const float* sa = &A[(size_t)(row0+ar)*K + kt + asub];
            asm volatile("cp.async.cg.shared.global [%0], [%1], 16;" :: "r"(da), "l"(sa));
            int br = c >> 5, bsub = (c & 31) * 4;
            unsigned db = (unsigned)__cvta_generic_to_shared(&Bs[buf][br][bsub]);
            const float* sb = &W[(size_t)(kt+br)*Nc + col0 + bsub];
            asm volatile("cp.async.cg.shared.global [%0], [%1], 16;" :: "r"(db), "l"(sb));
        }
        asm volatile("cp.async.commit_group;");
    };

    const int T = K >> 4;
    loadtile(0, 0);
    if (T > 1) loadtile(16, 1);

    for (int t = 0; t < T; t++) {
        if (t + 1 < T) asm volatile("cp.async.wait_group 1;");
        else           asm volatile("cp.async.wait_group 0;");
        __syncthreads();
        const int buf = t & 1;
#pragma unroll
        for (int k = 0; k < 16; k++) {
            float a[8], bb[8];
#pragma unroll
            for (int i = 0; i < 4; i++) {
                a[i]   = As[buf][ty*4 + i][k];
                a[i+4] = As[buf][64 + ty*4 + i][k];
            }
            float4 b0 = *reinterpret_cast<const float4*>(&Bs[buf][k][tx*4]);
            float4 b1 = *reinterpret_cast<const float4*>(&Bs[buf][k][64 + tx*4]);
            bb[0]=b0.x;bb[1]=b0.y;bb[2]=b0.z;bb[3]=b0.w;bb[4]=b1.x;bb[5]=b1.y;bb[6]=b1.z;bb[7]=b1.w;
#pragma unroll
            for (int i = 0; i < 8; i++)
#pragma unroll
                for (int j = 0; j < 8; j++) acc[i][j] = fmaf(a[i], bb[j], acc[i][j]);
        }
        __syncthreads();
        if (t + 2 < T) loadtile((t+2)*16, buf);
    }

    float cs[8], cq[8];
#pragma unroll
    for (int j = 0; j < 8; j++) { cs[j] = 0.f; cq[j] = 0.f; }
#pragma unroll
    for (int i = 0; i < 8; i++) {
        int r = row0 + ty*4 + (i < 4 ? i : 60 + i);
#pragma unroll
        for (int j = 0; j < 8; j++) {
            int c = col0 + tx*4 + (j < 4 ? j : 60 + j);
            float v = acc[i][j];
            if (bias) v += bias[c];
            if (res)  v += res[(size_t)r*Nc + c];
            if (relu) v = fmaxf(v, 0.f);
            C[(size_t)r*Nc + c] = v;
            cs[j] += v;
            cq[j] = fmaf(v, v, cq[j]);
        }
    }
    if (bnstats) {
        float* red1 = &As[0][0][0];      // reuse smem: 16x128
        float* red2 = &Bs[0][0][0];
        __syncthreads();
#pragma unroll
        for (int j = 0; j < 8; j++) {
            int c = tx*4 + (j < 4 ? j : 60 + j);
            red1[ty*128 + c] = cs[j];
            red2[ty*128 + c] = cq[j];
        }
        __syncthreads();
        if (tid < 128) {
            float ssum = 0.f, ssq = 0.f;
#pragma unroll
            for (int t = 0; t < 16; t++) { ssum += red1[t*128 + tid]; ssq += red2[t*128 + tid]; }
            g_part32[0][blockIdx.y][tid] = ssum;
            g_part32[1][blockIdx.y][tid] = ssq;
        }
    }
}

// ---------------------------------------------------------------------------
// Fused MHA v3 (R7 proven version): one block per (b,h), 256 threads.
// ---------------------------------------------------------------------------
#define ATTN_SMEM_BYTES ((3*1700 + 10000) * 4)
__global__ __launch_bounds__(256)
void attn_kernel(const float* __restrict__ qkv, float* __restrict__ o) {
    extern __shared__ float asm_[];
    float* qsh = asm_;            // 100*17
    float* ksh = qsh + 1700;      // 100*17
    float* vsh = ksh + 1700;      // 100*17
    float* psh = vsh + 1700;      // 100*100
    int bh = blockIdx.x;
    int b = bh >> 3, hh = bh & 7;
    int tid = threadIdx.x;
    for (int i = tid; i < 1600; i += 256) {
        int m = i >> 4, d = i & 15;
        const float* base = qkv + (size_t)(b*N + m) * TD + hh*16 + d;
        qsh[m*17 + d] = base[0];
        ksh[m*17 + d] = base[D];
        vsh[m*17 + d] = base[2*D];
    }
    __syncthreads();
    int w = tid >> 5, lane = tid & 31;
    for (int n = w; n < 100; n += 8) {
        float qreg[16];
        const float* qp = qsh + n*17;
#pragma unroll
        for (int d = 0; d < 16; d++) qreg[d] = qp[d];
        float sc[4];
        float mx = -1e30f;
#pragma unroll
        for (int j = 0; j < 4; j++) {
            int m = lane + 32*j;
            if (m < 100) {
                const float* kp = ksh + m*17;
                float a0 = 0.f, a1 = 0.f;
#pragma unroll
                for (int d = 0; d < 16; d += 2) {
                    a0 = fmaf(qreg[d],   kp[d],   a0);
                    a1 = fmaf(qreg[d+1], kp[d+1], a1);
                }
                sc[j] = (a0 + a1) * 0.25f;
                mx = fmaxf(mx, sc[j]);
            } else sc[j] = -1e30f;
        }
#pragma unroll
        for (int off = 16; off; off >>= 1) mx = fmaxf(mx, __shfl_xor_sync(0xffffffffu, mx, off));
        double sum = 0.0, ev[4];
#pragma unroll
        for (int j = 0; j < 4; j++) {
            int m = lane + 32*j;
            if (m < 100) { ev[j] = exp((double)(sc[j] - mx)); sum += ev[j]; }
            else ev[j] = 0.0;
        }
#pragma unroll
        for (int off = 16; off; off >>= 1) sum += __shfl_xor_sync(0xffffffffu, sum, off);
        double inv = 1.0 / sum;
#pragma unroll
        for (int j = 0; j < 4; j++) {
            int m = lane + 32*j;
            if (m < 100) psh[n*100 + m] = (float)(ev[j] * inv);
        }
    }
    __syncthreads();
    for (int idx = tid; idx < 1600; idx += 256) {
        int n = idx >> 4, dk = idx & 15;
        const float* pp = psh + n*100;
        const float* vp = vsh + dk;
        float a0 = 0.f, a1 = 0.f;
#pragma unroll 4
        for (int m = 0; m < 100; m += 2) {
            a0 = fmaf(pp[m],   vp[(m)*17],   a0);
            a1 = fmaf(pp[m+1], vp[(m+1)*17], a1);
        }
        o[(size_t)(b*N + n) * D + hh*16 + dk] = a0 + a1;
    }
}

// ---------------------------------------------------------------------------
// BN finalize: reduce 400 per-block partials (double), store mean/rstd.
// ---------------------------------------------------------------------------
__global__ void bn_stats2_kernel() {
    int c = threadIdx.x;
    double a = 0.0, q = 0.0;
    for (int p = 0; p < 400; p++) { a += (double)g_part32[0][p][c]; q += (double)g_part32[1][p][c]; }
    double mean = a * (1.0 / (double)M_ROWS);
    double var  = q * (1.0 / (double)M_ROWS) - mean*mean;
    g_mean[c] = mean;
    g_rstd[c] = 1.0 / sqrt(var + 1e-5);
}
__global__ void bn_apply_kernel(const float* __restrict__ s, const float* __restrict__ gb,
                                float* __restrict__ h) {
    int idx = blockIdx.x * blockDim.x + threadIdx.x;
    if (idx >= M_ROWS * D) return;
    int d = idx & 127;
    double v = (double)gb[d] * ((double)s[idx] - g_mean[d]) * g_rstd[d] + (double)gb[D + d];
    h[idx] = (float)v;
}

// ---------------------------------------------------------------------------
// wphw[d] = Wph @ Wstep (column d)
// ---------------------------------------------------------------------------
__global__ void wphw_kernel(const float* __restrict__ Wph, const float* __restrict__ Wstep) {
    int d = threadIdx.x;
    double a0 = 0.0, a1 = 0.0;
    for (int k = 0; k < 2*D; k += 2) {
        a0 = fma((double)Wph[k],   (double)Wstep[(k)*D + d],   a0);
        a1 = fma((double)Wph[k+1], (double)Wstep[(k+1)*D + d], a1);
    }
    g_wphw[d] = a0 + a1;
}

// ---------------------------------------------------------------------------
// Per-batch: hm = mean_n(h); fc = hm @ Wf; q0 = fc + wphw
// ---------------------------------------------------------------------------
__global__ void meanfix_kernel(const float* __restrict__ Wf) {
    __shared__ float sh[D];
    int b = blockIdx.x, d = threadIdx.x;
    double a = 0.0;
    for (int n = 0; n < N; n++) a += (double)g_h[(size_t)(b*N + n) * D + d];
    sh[d] = (float)(a * (1.0 / (double)N));
    __syncthreads();
    double fc = 0.0;
    for (int k = 0; k < D; k++) fc = fma((double)sh[k], (double)Wf[k*D + d], fc);
    g_fc[b*D + d] = (float)fc;
    g_q0[b*D + d] = (float)(fc + g_wphw[d]);
}

// ---------------------------------------------------------------------------
// Persistent greedy decode (unchanged). 512 threads, 2 blocks/SM.
// ---------------------------------------------------------------------------
#define HPS2 257
#define DEC_SMEM_BYTES (16 + (N*HPS2 + 128 + 128 + 800 + 128 + 128 + 512 + 100)*4 + 202*4)

__global__ __launch_bounds__(512, 2)
void decode_kernel(const float* __restrict__ x,
                   const float* __restrict__ Wout,
                   float* __restrict__ out) {
    extern __shared__ double dsm[];
    double* sh_ll  = dsm;
    float* sh_hp   = (float*)(dsm + 2);     // 100*257 (gK | gV)
    float* sh_q    = sh_hp + N*HPS2;
    float* sh_qb   = sh_q + D;
    float* sh_c    = sh_qb + D;
    float* sh_g    = sh_c + 800;
    float* sh_g2   = sh_g + D;
    float* sh_part = sh_g2 + D;
    float* sh_lg   = sh_part + 512;
    int*   sh_mask = (int*)(sh_lg + 100);
    int*   sh_pi   = sh_mask + 100;
    int*   sh_ctrl = sh_pi + 100;

    const float NF = 0.08838834764831843f;
    int b = blockIdx.x, tid = threadIdx.x;
    int w = tid >> 5, lane = tid & 31;
    int dd = tid & 127, part = tid >> 7;
    const float* lKg = g_3d + (size_t)b * (N*TD) + 2*D;

    for (int i = tid; i < N*256; i += 512) {
        int n = i >> 8, j = i & 255;
        sh_hp[n*HPS2 + j] = g_3d[(size_t)b * (N*TD) + n*TD + j];
    }
    if (tid < N) sh_mask[tid] = 0;
    if (tid == 0) { sh_ll[0] = 0.0; sh_ctrl[0] = 0; sh_ctrl[1] = 0; }
    __syncthreads();

    for (int s = 0; s < N; s++) {
        if (tid < 128) {
            if (s == 0) {
                sh_q[tid] = g_q0[b*D + tid];
            } else {
                float qb;
                if (s == 1) {
                    qb = g_fc[b*D + tid] + g_ef[(size_t)(b*N + sh_ctrl[0]) * D + tid];
                    sh_qb[tid] = qb;
                } else qb = sh_qb[tid];
                sh_q[tid] = qb + g_ed[(size_t)(b*N + sh_ctrl[1]) * D + tid];
            }
        }
        __syncthreads();
        for (int idx = tid; idx < 800; idx += 512) {
            int hh = idx / 100, n = idx - hh*100;
            const float* kp = sh_hp + n*HPS2 + hh*16;
            const float* qp = sh_q + hh*16;
            float a0 = 0.f, a1 = 0.f;
#pragma unroll
            for (int d2 = 0; d2 < 16; d2 += 2) {
                a0 = fmaf(qp[d2],   kp[d2],   a0);
                a1 = fmaf(qp[d2+1], kp[d2+1], a1);
            }
            sh_c[idx] = sh_mask[n] ? NEGV : (a0 + a1) * NF;
        }
        __syncthreads();
        if (w < 8) {
            int head = w;
            float mx = -1e30f;
            for (int n = lane; n < 100; n += 32) mx = fmaxf(mx, sh_c[head*100 + n]);
#pragma unroll
            for (int off = 16; off; off >>= 1) mx = fmaxf(mx, __shfl_xor_sync(0xffffffffu, mx, off));
            double sum = 0.0, ev[4];
#pragma unroll
            for (int j = 0; j < 4; j++) {
                int n = lane + 32*j;
                if (n < 100) { ev[j] = exp((double)(sh_c[head*100 + n] - mx)); sum += ev[j]; }
                else ev[j] = 0.0;
            }
#pragma unroll
            for (int off = 16; off; off >>= 1) sum += __shfl_xor_sync(0xffffffffu, sum, off);
            double inv = 1.0 / sum;
#pragma unroll
            for (int j = 0; j < 4; j++) {
                int n = lane + 32*j;
                if (n < 100) sh_c[head*100 + n] = (float)(ev[j] * inv);
            }
        }
        __syncthreads();
        {
            int hh = dd >> 4;
            const float* pp = sh_c + hh*100 + part*25;
            const float* vp = sh_hp + (size_t)(part*25) * HPS2 + D + dd;
            float a0 = 0.f, a1 = 0.f;
#pragma unroll 4
            for (int n = 0; n < 24; n += 2) {
                a0 = fmaf(pp[n],   vp[(n)*HPS2],   a0);
                a1 = fmaf(pp[n+1], vp[(n+1)*HPS2], a1);
            }
            a0 = fmaf(pp[24], vp[24*HPS2], a0);
            sh_part[tid] = a0 + a1;
        }
        __syncthreads();
        if (tid < 128) sh_g[tid] = sh_part[tid] + sh_part[tid+128] + sh_part[tid+256] + sh_part[tid+384];
        __syncthreads();
        {
            int k0 = part * 32;
            float a0 = 0.f, a1 = 0.f;
#pragma unroll 4
            for (int k = 0; k < 32; k += 2) {
                a0 = fmaf(sh_g[k0+k],   __ldg(&Wout[(k0+k)*D + dd]),   a0);
                a1 = fmaf(sh_g[k0+k+1], __ldg(&Wout[(k0+k+1)*D + dd]), a1);
            }
            sh_part[tid] = a0 + a1;
        }
        __syncthreads();
        if (tid < 128) sh_g2[tid] = sh_part[tid] + sh_part[tid+128] + sh_part[tid+256] + sh_part[tid+384];
        __syncthreads();
        if (dd < 100) {
            int k0 = part * 32;
            const float* lp = lKg + (size_t)dd * TD + k0;
            float a0 = 0.f, a1 = 0.f;
#pragma unroll
            for (int q4 = 0; q4 < 8; q4++) {
                float4 v = __ldg(reinterpret_cast<const float4*>(lp + q4*4));
                float4 g = *reinterpret_cast<const float4*>(&sh_g2[k0 + q4*4]);
                a0 = fmaf(g.x, v.x, a0); a1 = fmaf(g.y, v.y, a1);
                a0 = fmaf(g.z, v.z, a0); a1 = fmaf(g.w, v.w, a1);
            }
            sh_part[tid] = a0 + a1;
        }
        __syncthreads();
        if (tid < 100) {
            double a = (double)(sh_part[tid] + sh_part[tid+128] + sh_part[tid+256] + sh_part[tid+384]);
            sh_lg[tid] = sh_mask[tid] ? NEGV : (float)(tanh(a * (double)NF) * CLIPV);
        }
        __syncthreads();
        if (w == 0) {
            float mx = -1e30f; int mi = N + 1;
            for (int n = lane; n < N; n += 32) {
                float v = sh_lg[n];
                if (v > mx) { mx = v; mi = n; }
            }
#pragma unroll
            for (int off = 16; off; off >>= 1) {
                float om = __shfl_xor_sync(0xffffffffu, mx, off);
                int   oi = __shfl_xor_sync(0xffffffffu, mi, off);
                if (om > mx || (om == mx && oi < mi)) { mx = om; mi = oi; }
            }
            double sum = 0.0;
            for (int n = lane; n < N; n += 32) sum += exp((double)sh_lg[n] - (double)mx);
#pragma unroll
            for (int off = 16; off; off >>= 1) sum += __shfl_xor_sync(0xffffffffu, sum, off);
            if (lane == 0) {
                double lse = (double)mx + log(sum);
                sh_ll[0] += (double)sh_lg[mi] - lse;
                sh_mask[mi] = 1;
                sh_ctrl[1] = mi;
                if (s == 0) sh_ctrl[0] = mi;
                sh_pi[s] = mi;
                out[2*B + b*N + s] = (float)mi;
            }
        }
        __syncthreads();
    }
    if (tid < N) {
        int a = sh_pi[tid], c = sh_pi[(tid + 1) % N];
        double dx = (double)x[(b*N + a)*2]     - (double)x[(b*N + c)*2];
        double dy = (double)x[(b*N + a)*2 + 1] - (double)x[(b*N + c)*2 + 1];
        sh_lg[tid] = (float)sqrt(dx*dx + dy*dy);
    }
    __syncthreads();
    if (tid == 0) {
        double cst = 0.0;
        for (int t = 0; t < N; t++) cst += (double)sh_lg[t];
        out[b] = (float)cst;
        out[B + b] = (float)sh_ll[0];
    }
}

// ---------------------------------------------------------------------------
extern "C" void kernel_launch(void* const* d_in, const int* in_sizes, int n_in,
                              void* d_out, int out_size) {
    const float* x        = (const float*)d_in[0];
    const float* init_W   = (const float*)d_in[1];
    const float* init_b   = (const float*)d_in[2];
    const float* qkv_W    = (const float*)d_in[3];
    const float* out_W    = (const float*)d_in[4];
    const float* bn1      = (const float*)d_in[5];
    const float* bn2      = (const float*)d_in[6];
    const float* ff1_W    = (const float*)d_in[7];
    const float* ff1_b    = (const float*)d_in[8];
    const float* ff2_W    = (const float*)d_in[9];
    const float* ff2_b    = (const float*)d_in[10];
    const float* Wph      = (const float*)d_in[11];
    const float* nodes_W  = (const float*)d_in[12];
    const float* fixed_W  = (const float*)d_in[13];
    const float* step_W   = (const float*)d_in[14];
    const float* pout_W   = (const float*)d_in[15];
    float* out = (float*)d_out;

    cudaFuncSetAttribute(decode_kernel, cudaFuncAttributeMaxDynamicSharedMemorySize,
                         DEC_SMEM_BYTES + 128);
    cudaFuncSetAttribute(attn_kernel, cudaFuncAttributeMaxDynamicSharedMemorySize,
                         ATTN_SMEM_BYTES + 128);

    float *p_h, *p_3d, *p_ff, *p_o, *p_s, *p_ef, *p_ed;
    cudaGetSymbolAddress((void**)&p_h,  g_h);
    cudaGetSymbolAddress((void**)&p_3d, g_3d);
    cudaGetSymbolAddress((void**)&p_ff, g_ff);
    cudaGetSymbolAddress((void**)&p_o,  g_o);
    cudaGetSymbolAddress((void**)&p_s,  g_s);
    cudaGetSymbolAddress((void**)&p_ef, g_ef);
    cudaGetSymbolAddress((void**)&p_ed, g_ed);

    const int EW = 256;
    int egrid = (M_ROWS * D + EW - 1) / EW;

    init_embed_kernel<<<egrid, EW>>>(x, init_W, init_b);
    wphw_kernel<<<1, 128>>>(Wph, step_W);

    for (int l = 0; l < 2; l++) {
        gemm32_kernel<<<dim3(TD/128, M_ROWS/128), 256>>>(
            p_h, qkv_W + (size_t)l*D*TD, nullptr, nullptr, p_3d, M_ROWS, D, TD, 0, 0);
        attn_kernel<<<B*H, 256, ATTN_SMEM_BYTES + 128>>>(p_3d, p_o);
        // s = o @ Wout + h, with fused BN stats
        gemm32_kernel<<<dim3(D/128, M_ROWS/128), 256>>>(
            p_o, out_W + (size_t)l*D*D, nullptr, p_h, p_s, M_ROWS, D, D, 0, 1);
        bn_stats2_kernel<<<1, 128>>>();
        bn_apply_kernel<<<egrid, EW>>>(p_s, bn1 + (size_t)l*2*D, p_h);
        gemm32_kernel<<<dim3(FF/128, M_ROWS/128), 256>>>(
            p_h, ff1_W + (size_t)l*D*FF, ff1_b + (size_t)l*FF, nullptr, p_ff, M_ROWS, D, FF, 1, 0);
        // s = ff1 @ W2 + b2 + h, with fused BN stats
        gemm32_kernel<<<dim3(D/128, M_ROWS/128), 256>>>(
            p_ff, ff2_W + (size_t)l*FF*D, ff2_b + (size_t)l*D, p_h, p_s, M_ROWS, FF, D, 0, 1);
        bn_stats2_kernel<<<1, 128>>>();
        bn_apply_kernel<<<egrid, EW>>>(p_s, bn2 + (size_t)l*2*D, p_h);
    }

    // decoder precompute
    gemm32_kernel<<<dim3(TD/128, M_ROWS/128), 256>>>(
        p_h, nodes_W, nullptr, nullptr, p_3d, M_ROWS, D, TD, 0, 0);
    gemm32_kernel<<<dim3(D/128, M_ROWS/128), 256>>>(
        p_h, step_W, nullptr, nullptr, p_ef, M_ROWS, D, D, 0, 0);
    gemm32_kernel<<<dim3(D/128, M_ROWS/128), 256>>>(
        p_h, step_W + (size_t)D*D, nullptr, nullptr, p_ed, M_ROWS, D, D, 0, 0);
    meanfix_kernel<<<B, D>>>(fixed_W);

    decode_kernel<<<B, 512, DEC_SMEM_BYTES + 128>>>(x, pout_W, out);
}